// round 10
// baseline (speedup 1.0000x reference)
#include <cuda_runtime.h>
#include <cuda_fp16.h>
#include <cstdint>
#include <math.h>

// ---------------- problem constants ----------------
#define BB   16
#define CC   64
#define WW   125000
#define TT   99
#define SS   100
#define RR   66          // padded rows
#define KK   1250        // GEMM K
#define NN   192         // 32 oc * 3 kh * 2 halves
#define BK   64          // K per stage
#define NST  20          // stages
#define MTILE 128

// ---------------- scratch ----------------
__device__ __half g_Dh[(size_t)BB * RR * SS * NN];   // 40.5 MB GEMM output (fp16)
// packed weights fp16: [stage][n=192][k=64]
__device__ __align__(16) __half g_B[NST * NN * BK];

// ---------------- helpers ----------------
__device__ __forceinline__ uint32_t smem_u32(const void* p) {
    uint32_t a;
    asm("{ .reg .u64 t; cvta.to.shared.u64 t, %1; cvt.u32.u64 %0, t; }" : "=r"(a) : "l"(p));
    return a;
}
#define LDSM4(r0,r1,r2,r3, addr) \
    asm volatile("ldmatrix.sync.aligned.m8n8.x4.shared.b16 {%0,%1,%2,%3}, [%4];" \
        : "=r"(r0),"=r"(r1),"=r"(r2),"=r"(r3) : "r"(addr))
#define CPASYNC16(dst, src) \
    asm volatile("cp.async.cg.shared.global [%0], [%1], 16;" :: "r"(dst), "l"(src))
#define CPCOMMIT() asm volatile("cp.async.commit_group;" ::: "memory")
#define CPWAIT0()  asm volatile("cp.async.wait_group 0;" ::: "memory")

// fp16-accumulate HMMA (full-rate on sm_103a legacy tensor pipe)
__device__ __forceinline__ void mma16816_f16(uint32_t* c, const uint32_t* a, const uint32_t* b) {
    asm volatile("mma.sync.aligned.m16n8k16.row.col.f16.f16.f16.f16 "
        "{%0,%1}, {%2,%3,%4,%5}, {%6,%7}, {%0,%1};"
        : "+r"(c[0]), "+r"(c[1])
        : "r"(a[0]), "r"(a[1]), "r"(a[2]), "r"(a[3]), "r"(b[0]), "r"(b[1]));
}

// ---------------- SMEM layout (dynamic) ----------------
// row stride 144B (128B data + 16B pad) -> ldmatrix / STS conflict-free
#define ASTRIDE 144
#define OFF_B   (128 * ASTRIDE)          // 18432
#define BUFSZ   (OFF_B + 192 * ASTRIDE)  // 46080
#define SMEM_BYTES (2 * BUFSZ)           // 92160

// ---------------- kernel 0: pack weights -> fp16, [stage][n][k64] ----------------
__global__ void pack_w_kernel(const float* __restrict__ conv_w) {
    int i = blockIdx.x * blockDim.x + threadIdx.x;
    if (i >= NST * NN * BK) return;
    int c = i / (NN * BK);
    int r = i - c * (NN * BK);
    int n = r >> 6;
    int k = r & 63;
    int kk = c * BK + k;
    int grp = n >> 5;          // 0..5
    int oc  = n & 31;
    int kh  = grp >> 1;
    int h   = grp & 1;
    float w = 0.0f;
    if (kk < KK) w = conv_w[oc * 7500 + kh * 2500 + h * 1250 + kk];
    g_B[i] = __float2half_rn(w);
}

// ---------------- kernel 1: fp16 HMMA segment GEMM, 512 threads ----------------
// fp16 accumulation within each 64-K stage, fp32 across stages.
__global__ __launch_bounds__(512, 1) void seg_gemm_mma(const float* __restrict__ x) {
    extern __shared__ char smem[];
    const uint32_t sb = smem_u32(smem);
    const int tid  = threadIdx.x;
    const int wid  = tid >> 5;
    const int lane = tid & 31;

    // ---- per-warp A rows: 8 consecutive rows; lane offset = lane*2 floats ----
    const int rowbase = wid * 8;
    const float* rowp[8];
#pragma unroll
    for (int i = 0; i < 8; i++) {
        int m = blockIdx.x * MTILE + rowbase + i;
        int b = m / (RR * SS);
        int rem = m - b * (RR * SS);
        int rr = rem / SS;
        int s  = rem - rr * SS;
        int ch = rr - 1; ch = ch < 0 ? 0 : (ch > 63 ? 63 : ch);
        rowp[i] = x + ((size_t)(b * CC + ch)) * WW + (size_t)s * KK + lane * 2;
    }

    // ---- warp tiling: 4x4 warp grid, each warp 32(M) x 48(N) ----
    const int warpM = (wid & 3) * 32;
    const int warpN = (wid >> 2) * 48;
    const uint32_t invA = (uint32_t)((warpM + (lane & 15)) * ASTRIDE + ((lane >> 4) * 16));
    const uint32_t invB = (uint32_t)((warpN + (lane & 7) + ((lane & 16) >> 1)) * ASTRIDE + ((lane & 8) << 1));

    float acc[2][6][4];
#pragma unroll
    for (int i = 0; i < 2; i++)
#pragma unroll
        for (int j = 0; j < 6; j++)
#pragma unroll
            for (int q = 0; q < 4; q++) acc[i][j][q] = 0.0f;

    float2 f2[8];   // one float2 per owned row

    auto loadA = [&](int c) {
        if (c < NST - 1) {
#pragma unroll
            for (int i = 0; i < 8; i++)
                f2[i] = *reinterpret_cast<const float2*>(rowp[i] + c * BK);
        } else {
            const int k0 = c * BK + lane * 2;   // 1250 is even -> whole float2 in or out
            if (k0 < KK) {
#pragma unroll
                for (int i = 0; i < 8; i++)
                    f2[i] = *reinterpret_cast<const float2*>(rowp[i] + c * BK);
            } else {
#pragma unroll
                for (int i = 0; i < 8; i++) f2[i] = make_float2(0.0f, 0.0f);
            }
        }
    };
    auto stsA = [&](int buf) {
        const uint32_t base = sb + buf * BUFSZ + rowbase * ASTRIDE + lane * 4;
#pragma unroll
        for (int i = 0; i < 8; i++) {
            __half2 hh = __floats2half2_rn(f2[i].x, f2[i].y);
            asm volatile("st.shared.b32 [%0], %1;"
                :: "r"(base + i * ASTRIDE), "r"(*reinterpret_cast<uint32_t*>(&hh)) : "memory");
        }
    };
    // B: 192 rows x 128B -> 1536 16B chunks via cp.async (3 per thread)
    auto loadB = [&](int c, int buf) {
#pragma unroll
        for (int i = 0; i < 3; i++) {
            int u = tid + 512 * i;
            int rowb = u >> 3, j = u & 7;
            uint32_t dst = sb + buf * BUFSZ + OFF_B + rowb * ASTRIDE + j * 16;
            const char* src = reinterpret_cast<const char*>(g_B) + ((size_t)c * NN + rowb) * 128 + j * 16;
            CPASYNC16(dst, src);
        }
    };

    auto compute = [&](int buf) {
        const uint32_t ab = sb + buf * BUFSZ;
        // per-stage fp16 accumulators (zeroed each stage)
        uint32_t acch[2][6][2];
#pragma unroll
        for (int i = 0; i < 2; i++)
#pragma unroll
            for (int j = 0; j < 6; j++) { acch[i][j][0] = 0u; acch[i][j][1] = 0u; }

#pragma unroll
        for (int g = 0; g < 4; g++) {
            uint32_t ah[8];
            LDSM4(ah[0], ah[1], ah[2], ah[3], ab + invA + g * 32);
            LDSM4(ah[4], ah[5], ah[6], ah[7], ab + invA + 16 * ASTRIDE + g * 32);
#pragma unroll
            for (int ng = 0; ng < 3; ng++) {
                uint32_t bf[4];
                LDSM4(bf[0], bf[1], bf[2], bf[3], ab + OFF_B + invB + ng * (16 * ASTRIDE) + g * 32);
#pragma unroll
                for (int mt = 0; mt < 2; mt++) {
                    mma16816_f16(acch[mt][ng * 2 + 0], ah + mt * 4, bf + 0);
                    mma16816_f16(acch[mt][ng * 2 + 1], ah + mt * 4, bf + 2);
                }
            }
        }
        // flush stage partials into fp32 accumulators
#pragma unroll
        for (int mt = 0; mt < 2; mt++)
#pragma unroll
            for (int nt = 0; nt < 6; nt++) {
                float2 lo = __half22float2(*reinterpret_cast<__half2*>(&acch[mt][nt][0]));
                float2 hi = __half22float2(*reinterpret_cast<__half2*>(&acch[mt][nt][1]));
                acc[mt][nt][0] += lo.x;
                acc[mt][nt][1] += lo.y;
                acc[mt][nt][2] += hi.x;
                acc[mt][nt][3] += hi.y;
            }
    };

    // ---- prologue ----
    loadA(0);
    loadB(0, 0);
    CPCOMMIT();
    stsA(0);
    CPWAIT0();
    __syncthreads();

    // ---- main loop ----
    for (int c = 0; c < NST; c++) {
        const int buf = c & 1;
        if (c < NST - 1) { loadA(c + 1); loadB(c + 1, buf ^ 1); CPCOMMIT(); }
        compute(buf);
        if (c < NST - 1) { stsA(buf ^ 1); CPWAIT0(); }
        __syncthreads();
    }

    // ---- write D (fp16) ----
    const int l4 = lane >> 2;
    const int l2 = (lane & 3) * 2;
#pragma unroll
    for (int mt = 0; mt < 2; mt++) {
        const int mrow = blockIdx.x * MTILE + warpM + mt * 16 + l4;
        __half* dbase = g_Dh + (size_t)mrow * NN + warpN + l2;
#pragma unroll
        for (int nt = 0; nt < 6; nt++) {
            *reinterpret_cast<__half2*>(dbase + nt * 8)          = __floats2half2_rn(acc[mt][nt][0], acc[mt][nt][1]);
            *reinterpret_cast<__half2*>(dbase + nt * 8 + 8 * NN) = __floats2half2_rn(acc[mt][nt][2], acc[mt][nt][3]);
        }
    }
}

// ---------------- kernel 2: fused combine + 1x1 conv + RNN scan + sigmoid ----------------
__global__ __launch_bounds__(128) void epi_rnn_kernel(
        const float* __restrict__ conv_b,  const float* __restrict__ conv2_w,
        const float* __restrict__ conv2_b,
        const float* __restrict__ w_ih, const float* __restrict__ w_hh,
        const float* __restrict__ b_ih, const float* __restrict__ b_hh,
        const float* __restrict__ h0,   float* __restrict__ out) {
    __shared__ float zs[TT];
    const int bc = blockIdx.x;
    const int b = bc >> 6;
    const int c = bc & 63;
    const int wid  = threadIdx.x >> 5;
    const int lane = threadIdx.x & 31;

    const float cb  = conv_b[lane];
    const float cw  = conv2_w[lane];
    const float cb2 = conv2_b[0];

    for (int t = wid; t < TT; t += 4) {
        float sum = 0.0f;
#pragma unroll
        for (int kh = 0; kh < 3; kh++) {
#pragma unroll
            for (int h = 0; h < 2; h++) {
                size_t row = ((size_t)(b * RR + (c + kh)) * SS + (t + h));
                sum += __half2float(g_Dh[row * NN + (kh * 2 + h) * 32 + lane]);
            }
        }
        float y = fmaxf(sum + cb, 0.0f);
        float v = y * cw;
#pragma unroll
        for (int o = 16; o > 0; o >>= 1)
            v += __shfl_xor_sync(0xffffffffu, v, o);
        if (lane == 0) zs[t] = fmaxf(v + cb2, 0.0f);
    }
    __syncthreads();

    if (threadIdx.x == 0) {
        const float wih  = w_ih[0];
        const float whh  = w_hh[0];
        const float bias = b_ih[0] + b_hh[0];
        float h = h0[b];
#pragma unroll 3
        for (int t = 0; t < TT; t++) {
            float a = fmaf(wih, zs[t], fmaf(whh, h, bias));
            float e = __expf(2.0f * a);
            h = 1.0f - __fdividef(2.0f, e + 1.0f);   // tanh(a)
        }
        out[bc] = __fdividef(1.0f, 1.0f + __expf(-h));
    }
}

// ---------------- launcher ----------------
extern "C" void kernel_launch(void* const* d_in, const int* in_sizes, int n_in,
                              void* d_out, int out_size) {
    const float* x       = (const float*)d_in[0];
    const float* conv_w  = (const float*)d_in[1];
    const float* conv_b  = (const float*)d_in[2];
    const float* conv2_w = (const float*)d_in[3];
    const float* conv2_b = (const float*)d_in[4];
    const float* w_ih    = (const float*)d_in[5];
    const float* w_hh    = (const float*)d_in[6];
    const float* b_ih    = (const float*)d_in[7];
    const float* b_hh    = (const float*)d_in[8];
    const float* h0      = (const float*)d_in[9];
    float* out = (float*)d_out;

    static int smem_set = 0;
    if (!smem_set) {
        cudaFuncSetAttribute(seg_gemm_mma, cudaFuncAttributeMaxDynamicSharedMemorySize, SMEM_BYTES);
        smem_set = 1;
    }

    pack_w_kernel<<<(NST * NN * BK + 255) / 256, 256>>>(conv_w);

    seg_gemm_mma<<<(BB * RR * SS) / MTILE, 512, SMEM_BYTES>>>(x);   // 825 CTAs

    epi_rnn_kernel<<<BB * CC, 128>>>(conv_b, conv2_w, conv2_b,
                                     w_ih, w_hh, b_ih, b_hh, h0, out);
}

// round 11
// speedup vs baseline: 1.2805x; 1.2805x over previous
#include <cuda_runtime.h>
#include <cuda_fp16.h>
#include <cstdint>
#include <math.h>

// ---------------- problem constants ----------------
#define BB   16
#define CC   64
#define WW   125000
#define TT   99
#define SS   100
#define RR   66          // padded rows
#define KK   1250        // GEMM K
#define NN   192         // 32 oc * 3 kh * 2 halves
#define BK   64          // K per stage
#define NST  20          // stages
#define MTILE 64

// ---------------- scratch ----------------
__device__ __half g_Dh[(size_t)BB * RR * SS * NN];   // 40.5 MB GEMM output (fp16)
// packed weights fp16: [stage][n=192][k=64]
__device__ __align__(16) __half g_B[NST * NN * BK];

// ---------------- helpers ----------------
__device__ __forceinline__ uint32_t smem_u32(const void* p) {
    uint32_t a;
    asm("{ .reg .u64 t; cvta.to.shared.u64 t, %1; cvt.u32.u64 %0, t; }" : "=r"(a) : "l"(p));
    return a;
}
#define LDSM4(r0,r1,r2,r3, addr) \
    asm volatile("ldmatrix.sync.aligned.m8n8.x4.shared.b16 {%0,%1,%2,%3}, [%4];" \
        : "=r"(r0),"=r"(r1),"=r"(r2),"=r"(r3) : "r"(addr))
#define CPASYNC16(dst, src) \
    asm volatile("cp.async.cg.shared.global [%0], [%1], 16;" :: "r"(dst), "l"(src))
#define CPCOMMIT() asm volatile("cp.async.commit_group;" ::: "memory")
#define CPWAIT0()  asm volatile("cp.async.wait_group 0;" ::: "memory")

__device__ __forceinline__ void mma16816(float* c, const uint32_t* a, const uint32_t* b) {
    asm volatile("mma.sync.aligned.m16n8k16.row.col.f32.f16.f16.f32 "
        "{%0,%1,%2,%3}, {%4,%5,%6,%7}, {%8,%9}, {%0,%1,%2,%3};"
        : "+f"(c[0]), "+f"(c[1]), "+f"(c[2]), "+f"(c[3])
        : "r"(a[0]), "r"(a[1]), "r"(a[2]), "r"(a[3]), "r"(b[0]), "r"(b[1]));
}

// ---------------- SMEM layout (dynamic) ----------------
// row stride 144B (128B data + 16B pad) -> ldmatrix / STS conflict-free
#define ASTRIDE 144
#define OFF_B   (MTILE * ASTRIDE)        // 9216
#define BUFSZ   (OFF_B + 192 * ASTRIDE)  // 36864
#define SMEM_BYTES (2 * BUFSZ)           // 73728  -> 2 CTAs/SM

// ---------------- kernel 0: pack weights -> fp16, [stage][n][k64] ----------------
__global__ void pack_w_kernel(const float* __restrict__ conv_w) {
    int i = blockIdx.x * blockDim.x + threadIdx.x;
    if (i >= NST * NN * BK) return;
    int c = i / (NN * BK);
    int r = i - c * (NN * BK);
    int n = r >> 6;
    int k = r & 63;
    int kk = c * BK + k;
    int grp = n >> 5;          // 0..5
    int oc  = n & 31;
    int kh  = grp >> 1;
    int h   = grp & 1;
    float w = 0.0f;
    if (kk < KK) w = conv_w[oc * 7500 + kh * 2500 + h * 1250 + kk];
    g_B[i] = __float2half_rn(w);
}

// ---------------- kernel 1: fp16 HMMA segment GEMM, 256 threads, 2 CTAs/SM ----------------
// A-load: warp w owns rows [8w, 8w+8); one warp-LDG.64 per row (coalesced).
__global__ __launch_bounds__(256, 2) void seg_gemm_mma(const float* __restrict__ x) {
    extern __shared__ char smem[];
    const uint32_t sb = smem_u32(smem);
    const int tid  = threadIdx.x;
    const int wid  = tid >> 5;
    const int lane = tid & 31;

    // ---- per-warp A rows: 8 consecutive rows; lane offset = lane*2 floats ----
    const int rowbase = wid * 8;
    const float* rowp[8];
#pragma unroll
    for (int i = 0; i < 8; i++) {
        int m = blockIdx.x * MTILE + rowbase + i;
        int b = m / (RR * SS);
        int rem = m - b * (RR * SS);
        int rr = rem / SS;
        int s  = rem - rr * SS;
        int ch = rr - 1; ch = ch < 0 ? 0 : (ch > 63 ? 63 : ch);
        rowp[i] = x + ((size_t)(b * CC + ch)) * WW + (size_t)s * KK + lane * 2;
    }

    // ---- warp tiling: 2(M) x 4(N) warp grid, each warp 32(M) x 48(N) ----
    const int warpM = (wid & 1) * 32;
    const int warpN = (wid >> 1) * 48;
    const uint32_t invA = (uint32_t)((warpM + (lane & 15)) * ASTRIDE + ((lane >> 4) * 16));
    const uint32_t invB = (uint32_t)((warpN + (lane & 7) + ((lane & 16) >> 1)) * ASTRIDE + ((lane & 8) << 1));

    float acc[2][6][4];
#pragma unroll
    for (int i = 0; i < 2; i++)
#pragma unroll
        for (int j = 0; j < 6; j++)
#pragma unroll
            for (int q = 0; q < 4; q++) acc[i][j][q] = 0.0f;

    float2 f2[8];   // one float2 per owned row

    auto loadA = [&](int c) {
        if (c < NST - 1) {
#pragma unroll
            for (int i = 0; i < 8; i++)
                f2[i] = *reinterpret_cast<const float2*>(rowp[i] + c * BK);
        } else {
            const int k0 = c * BK + lane * 2;   // 1250 even -> whole float2 in or out
            if (k0 < KK) {
#pragma unroll
                for (int i = 0; i < 8; i++)
                    f2[i] = *reinterpret_cast<const float2*>(rowp[i] + c * BK);
            } else {
#pragma unroll
                for (int i = 0; i < 8; i++) f2[i] = make_float2(0.0f, 0.0f);
            }
        }
    };
    auto stsA = [&](int buf) {
        const uint32_t base = sb + buf * BUFSZ + rowbase * ASTRIDE + lane * 4;
#pragma unroll
        for (int i = 0; i < 8; i++) {
            __half2 hh = __floats2half2_rn(f2[i].x, f2[i].y);
            asm volatile("st.shared.b32 [%0], %1;"
                :: "r"(base + i * ASTRIDE), "r"(*reinterpret_cast<uint32_t*>(&hh)) : "memory");
        }
    };
    // B: 192 rows x 128B -> 1536 16B chunks via cp.async (6 per thread)
    auto loadB = [&](int c, int buf) {
#pragma unroll
        for (int i = 0; i < 6; i++) {
            int u = tid + 256 * i;
            int rowb = u >> 3, j = u & 7;
            uint32_t dst = sb + buf * BUFSZ + OFF_B + rowb * ASTRIDE + j * 16;
            const char* src = reinterpret_cast<const char*>(g_B) + ((size_t)c * NN + rowb) * 128 + j * 16;
            CPASYNC16(dst, src);
        }
    };

    auto compute = [&](int buf) {
        const uint32_t ab = sb + buf * BUFSZ;
#pragma unroll
        for (int g = 0; g < 4; g++) {
            uint32_t ah[8];
            LDSM4(ah[0], ah[1], ah[2], ah[3], ab + invA + g * 32);
            LDSM4(ah[4], ah[5], ah[6], ah[7], ab + invA + 16 * ASTRIDE + g * 32);
#pragma unroll
            for (int ng = 0; ng < 3; ng++) {
                uint32_t bf[4];
                LDSM4(bf[0], bf[1], bf[2], bf[3], ab + OFF_B + invB + ng * (16 * ASTRIDE) + g * 32);
#pragma unroll
                for (int mt = 0; mt < 2; mt++) {
                    mma16816(acc[mt][ng * 2 + 0], ah + mt * 4, bf + 0);
                    mma16816(acc[mt][ng * 2 + 1], ah + mt * 4, bf + 2);
                }
            }
        }
    };

    // ---- prologue ----
    loadA(0);
    loadB(0, 0);
    CPCOMMIT();
    stsA(0);
    CPWAIT0();
    __syncthreads();

    // ---- main loop ----
    for (int c = 0; c < NST; c++) {
        const int buf = c & 1;
        if (c < NST - 1) { loadA(c + 1); loadB(c + 1, buf ^ 1); CPCOMMIT(); }
        compute(buf);
        if (c < NST - 1) { stsA(buf ^ 1); CPWAIT0(); }
        __syncthreads();
    }

    // ---- write D (fp16) ----
    const int l4 = lane >> 2;
    const int l2 = (lane & 3) * 2;
#pragma unroll
    for (int mt = 0; mt < 2; mt++) {
        const int mrow = blockIdx.x * MTILE + warpM + mt * 16 + l4;
        __half* dbase = g_Dh + (size_t)mrow * NN + warpN + l2;
#pragma unroll
        for (int nt = 0; nt < 6; nt++) {
            *reinterpret_cast<__half2*>(dbase + nt * 8)          = __floats2half2_rn(acc[mt][nt][0], acc[mt][nt][1]);
            *reinterpret_cast<__half2*>(dbase + nt * 8 + 8 * NN) = __floats2half2_rn(acc[mt][nt][2], acc[mt][nt][3]);
        }
    }
}

// ---------------- kernel 2: fused combine + 1x1 conv + RNN scan + sigmoid ----------------
__global__ __launch_bounds__(128) void epi_rnn_kernel(
        const float* __restrict__ conv_b,  const float* __restrict__ conv2_w,
        const float* __restrict__ conv2_b,
        const float* __restrict__ w_ih, const float* __restrict__ w_hh,
        const float* __restrict__ b_ih, const float* __restrict__ b_hh,
        const float* __restrict__ h0,   float* __restrict__ out) {
    __shared__ float zs[TT];
    const int bc = blockIdx.x;
    const int b = bc >> 6;
    const int c = bc & 63;
    const int wid  = threadIdx.x >> 5;
    const int lane = threadIdx.x & 31;

    const float cb  = conv_b[lane];
    const float cw  = conv2_w[lane];
    const float cb2 = conv2_b[0];

    for (int t = wid; t < TT; t += 4) {
        float sum = 0.0f;
#pragma unroll
        for (int kh = 0; kh < 3; kh++) {
#pragma unroll
            for (int h = 0; h < 2; h++) {
                size_t row = ((size_t)(b * RR + (c + kh)) * SS + (t + h));
                sum += __half2float(g_Dh[row * NN + (kh * 2 + h) * 32 + lane]);
            }
        }
        float y = fmaxf(sum + cb, 0.0f);
        float v = y * cw;
#pragma unroll
        for (int o = 16; o > 0; o >>= 1)
            v += __shfl_xor_sync(0xffffffffu, v, o);
        if (lane == 0) zs[t] = fmaxf(v + cb2, 0.0f);
    }
    __syncthreads();

    if (threadIdx.x == 0) {
        const float wih  = w_ih[0];
        const float whh  = w_hh[0];
        const float bias = b_ih[0] + b_hh[0];
        float h = h0[b];
#pragma unroll 3
        for (int t = 0; t < TT; t++) {
            float a = fmaf(wih, zs[t], fmaf(whh, h, bias));
            float e = __expf(2.0f * a);
            h = 1.0f - __fdividef(2.0f, e + 1.0f);   // tanh(a)
        }
        out[bc] = __fdividef(1.0f, 1.0f + __expf(-h));
    }
}

// ---------------- launcher ----------------
extern "C" void kernel_launch(void* const* d_in, const int* in_sizes, int n_in,
                              void* d_out, int out_size) {
    const float* x       = (const float*)d_in[0];
    const float* conv_w  = (const float*)d_in[1];
    const float* conv_b  = (const float*)d_in[2];
    const float* conv2_w = (const float*)d_in[3];
    const float* conv2_b = (const float*)d_in[4];
    const float* w_ih    = (const float*)d_in[5];
    const float* w_hh    = (const float*)d_in[6];
    const float* b_ih    = (const float*)d_in[7];
    const float* b_hh    = (const float*)d_in[8];
    const float* h0      = (const float*)d_in[9];
    float* out = (float*)d_out;

    static int smem_set = 0;
    if (!smem_set) {
        cudaFuncSetAttribute(seg_gemm_mma, cudaFuncAttributeMaxDynamicSharedMemorySize, SMEM_BYTES);
        smem_set = 1;
    }

    pack_w_kernel<<<(NST * NN * BK + 255) / 256, 256>>>(conv_w);

    seg_gemm_mma<<<(BB * RR * SS) / MTILE, 256, SMEM_BYTES>>>(x);   // 1650 CTAs

    epi_rnn_kernel<<<BB * CC, 128>>>(conv_b, conv2_w, conv2_b,
                                     w_ih, w_hh, b_ih, b_hh, h0, out);
}

// round 12
// speedup vs baseline: 1.2911x; 1.0083x over previous
#include <cuda_runtime.h>
#include <cuda_fp16.h>
#include <cstdint>
#include <math.h>

// ---------------- problem constants ----------------
#define BB   16
#define CC   64
#define WW   125000
#define TT   99
#define SS   100
#define KK   1250        // GEMM K
#define NN   192         // 32 oc * 3 kh * 2 halves
#define BK   64          // K per stage
#define NST  20          // stages
#define MTILE 64
// M-space: distinct (b, ch, s) only -> 16*64*100 = 102400 rows (no padded dups)
#define MM   (BB * CC * SS)

// ---------------- scratch ----------------
__device__ __half g_Dh[(size_t)MM * NN];             // 39.3 MB GEMM output (fp16)
// packed weights fp16: [stage][n=192][k=64]
__device__ __align__(16) __half g_B[NST * NN * BK];

// ---------------- helpers ----------------
__device__ __forceinline__ uint32_t smem_u32(const void* p) {
    uint32_t a;
    asm("{ .reg .u64 t; cvta.to.shared.u64 t, %1; cvt.u32.u64 %0, t; }" : "=r"(a) : "l"(p));
    return a;
}
#define LDSM4(r0,r1,r2,r3, addr) \
    asm volatile("ldmatrix.sync.aligned.m8n8.x4.shared.b16 {%0,%1,%2,%3}, [%4];" \
        : "=r"(r0),"=r"(r1),"=r"(r2),"=r"(r3) : "r"(addr))
#define CPASYNC16(dst, src) \
    asm volatile("cp.async.cg.shared.global [%0], [%1], 16;" :: "r"(dst), "l"(src))
#define CPCOMMIT() asm volatile("cp.async.commit_group;" ::: "memory")
#define CPWAIT0()  asm volatile("cp.async.wait_group 0;" ::: "memory")

__device__ __forceinline__ void mma16816(float* c, const uint32_t* a, const uint32_t* b) {
    asm volatile("mma.sync.aligned.m16n8k16.row.col.f32.f16.f16.f32 "
        "{%0,%1,%2,%3}, {%4,%5,%6,%7}, {%8,%9}, {%0,%1,%2,%3};"
        : "+f"(c[0]), "+f"(c[1]), "+f"(c[2]), "+f"(c[3])
        : "r"(a[0]), "r"(a[1]), "r"(a[2]), "r"(a[3]), "r"(b[0]), "r"(b[1]));
}

// ---------------- SMEM layout (dynamic) ----------------
// row stride 144B (128B data + 16B pad) -> ldmatrix / STS conflict-free
#define ASTRIDE 144
#define OFF_B   (MTILE * ASTRIDE)        // 9216
#define BUFSZ   (OFF_B + 192 * ASTRIDE)  // 36864
#define SMEM_BYTES (2 * BUFSZ)           // 73728  -> 2 CTAs/SM

// ---------------- kernel 0: pack weights -> fp16, [stage][n][k64] ----------------
__global__ void pack_w_kernel(const float* __restrict__ conv_w) {
    int i = blockIdx.x * blockDim.x + threadIdx.x;
    if (i >= NST * NN * BK) return;
    int c = i / (NN * BK);
    int r = i - c * (NN * BK);
    int n = r >> 6;
    int k = r & 63;
    int kk = c * BK + k;
    int grp = n >> 5;          // 0..5
    int oc  = n & 31;
    int kh  = grp >> 1;
    int h   = grp & 1;
    float w = 0.0f;
    if (kk < KK) w = conv_w[oc * 7500 + kh * 2500 + h * 1250 + kk];
    g_B[i] = __float2half_rn(w);
}

// ---------------- kernel 1: fp16 HMMA segment GEMM, 256 threads, 2 CTAs/SM ----------------
// M row m = (b*64 + ch)*100 + s  (distinct channels only, no pad dups)
__global__ __launch_bounds__(256, 2) void seg_gemm_mma(const float* __restrict__ x) {
    extern __shared__ char smem[];
    const uint32_t sb = smem_u32(smem);
    const int tid  = threadIdx.x;
    const int wid  = tid >> 5;
    const int lane = tid & 31;

    // ---- per-warp A rows: 8 consecutive rows; lane offset = lane*2 floats ----
    const int rowbase = wid * 8;
    const float* rowp[8];
#pragma unroll
    for (int i = 0; i < 8; i++) {
        int m = blockIdx.x * MTILE + rowbase + i;
        int bc = m / SS;            // b*64 + ch
        int s  = m - bc * SS;
        rowp[i] = x + (size_t)bc * WW + (size_t)s * KK + lane * 2;
    }

    // ---- warp tiling: 2(M) x 4(N) warp grid, each warp 32(M) x 48(N) ----
    const int warpM = (wid & 1) * 32;
    const int warpN = (wid >> 1) * 48;
    const uint32_t invA = (uint32_t)((warpM + (lane & 15)) * ASTRIDE + ((lane >> 4) * 16));
    const uint32_t invB = (uint32_t)((warpN + (lane & 7) + ((lane & 16) >> 1)) * ASTRIDE + ((lane & 8) << 1));

    float acc[2][6][4];
#pragma unroll
    for (int i = 0; i < 2; i++)
#pragma unroll
        for (int j = 0; j < 6; j++)
#pragma unroll
            for (int q = 0; q < 4; q++) acc[i][j][q] = 0.0f;

    float2 f2[8];   // one float2 per owned row

    auto loadA = [&](int c) {
        if (c < NST - 1) {
#pragma unroll
            for (int i = 0; i < 8; i++)
                f2[i] = *reinterpret_cast<const float2*>(rowp[i] + c * BK);
        } else {
            const int k0 = c * BK + lane * 2;   // 1250 even -> whole float2 in or out
            if (k0 < KK) {
#pragma unroll
                for (int i = 0; i < 8; i++)
                    f2[i] = *reinterpret_cast<const float2*>(rowp[i] + c * BK);
            } else {
#pragma unroll
                for (int i = 0; i < 8; i++) f2[i] = make_float2(0.0f, 0.0f);
            }
        }
    };
    auto stsA = [&](int buf) {
        const uint32_t base = sb + buf * BUFSZ + rowbase * ASTRIDE + lane * 4;
#pragma unroll
        for (int i = 0; i < 8; i++) {
            __half2 hh = __floats2half2_rn(f2[i].x, f2[i].y);
            asm volatile("st.shared.b32 [%0], %1;"
                :: "r"(base + i * ASTRIDE), "r"(*reinterpret_cast<uint32_t*>(&hh)) : "memory");
        }
    };
    // B: 192 rows x 128B -> 1536 16B chunks via cp.async (6 per thread)
    auto loadB = [&](int c, int buf) {
#pragma unroll
        for (int i = 0; i < 6; i++) {
            int u = tid + 256 * i;
            int rowb = u >> 3, j = u & 7;
            uint32_t dst = sb + buf * BUFSZ + OFF_B + rowb * ASTRIDE + j * 16;
            const char* src = reinterpret_cast<const char*>(g_B) + ((size_t)c * NN + rowb) * 128 + j * 16;
            CPASYNC16(dst, src);
        }
    };

    auto compute = [&](int buf) {
        const uint32_t ab = sb + buf * BUFSZ;
#pragma unroll
        for (int g = 0; g < 4; g++) {
            uint32_t ah[8];
            LDSM4(ah[0], ah[1], ah[2], ah[3], ab + invA + g * 32);
            LDSM4(ah[4], ah[5], ah[6], ah[7], ab + invA + 16 * ASTRIDE + g * 32);
#pragma unroll
            for (int ng = 0; ng < 3; ng++) {
                uint32_t bf[4];
                LDSM4(bf[0], bf[1], bf[2], bf[3], ab + OFF_B + invB + ng * (16 * ASTRIDE) + g * 32);
#pragma unroll
                for (int mt = 0; mt < 2; mt++) {
                    mma16816(acc[mt][ng * 2 + 0], ah + mt * 4, bf + 0);
                    mma16816(acc[mt][ng * 2 + 1], ah + mt * 4, bf + 2);
                }
            }
        }
    };

    // ---- prologue ----
    loadA(0);
    loadB(0, 0);
    CPCOMMIT();
    stsA(0);
    CPWAIT0();
    __syncthreads();

    // ---- main loop ----
    for (int c = 0; c < NST; c++) {
        const int buf = c & 1;
        if (c < NST - 1) { loadA(c + 1); loadB(c + 1, buf ^ 1); CPCOMMIT(); }
        compute(buf);
        if (c < NST - 1) { stsA(buf ^ 1); CPWAIT0(); }
        __syncthreads();
    }

    // ---- write D (fp16) ----
    const int l4 = lane >> 2;
    const int l2 = (lane & 3) * 2;
#pragma unroll
    for (int mt = 0; mt < 2; mt++) {
        const int mrow = blockIdx.x * MTILE + warpM + mt * 16 + l4;
        __half* dbase = g_Dh + (size_t)mrow * NN + warpN + l2;
#pragma unroll
        for (int nt = 0; nt < 6; nt++) {
            *reinterpret_cast<__half2*>(dbase + nt * 8)          = __floats2half2_rn(acc[mt][nt][0], acc[mt][nt][1]);
            *reinterpret_cast<__half2*>(dbase + nt * 8 + 8 * NN) = __floats2half2_rn(acc[mt][nt][2], acc[mt][nt][3]);
        }
    }
}

// ---------------- kernel 2: fused combine + 1x1 conv + RNN scan + sigmoid ----------------
// D row for (b, c+kh, t+h): channel ch = clamp(c+kh-1, 0, 63), row = (b*64+ch)*100 + t+h
__global__ __launch_bounds__(128) void epi_rnn_kernel(
        const float* __restrict__ conv_b,  const float* __restrict__ conv2_w,
        const float* __restrict__ conv2_b,
        const float* __restrict__ w_ih, const float* __restrict__ w_hh,
        const float* __restrict__ b_ih, const float* __restrict__ b_hh,
        const float* __restrict__ h0,   float* __restrict__ out) {
    __shared__ float zs[TT];
    const int bc = blockIdx.x;
    const int b = bc >> 6;
    const int c = bc & 63;
    const int wid  = threadIdx.x >> 5;
    const int lane = threadIdx.x & 31;

    const float cb  = conv_b[lane];
    const float cw  = conv2_w[lane];
    const float cb2 = conv2_b[0];

    // clamped channel rows for kh = 0,1,2
    int chrow[3];
#pragma unroll
    for (int kh = 0; kh < 3; kh++) {
        int ch = c + kh - 1; ch = ch < 0 ? 0 : (ch > 63 ? 63 : ch);
        chrow[kh] = b * CC + ch;
    }

    for (int t = wid; t < TT; t += 4) {
        float sum = 0.0f;
#pragma unroll
        for (int kh = 0; kh < 3; kh++) {
#pragma unroll
            for (int h = 0; h < 2; h++) {
                size_t row = (size_t)chrow[kh] * SS + (t + h);
                sum += __half2float(g_Dh[row * NN + (kh * 2 + h) * 32 + lane]);
            }
        }
        float y = fmaxf(sum + cb, 0.0f);
        float v = y * cw;
#pragma unroll
        for (int o = 16; o > 0; o >>= 1)
            v += __shfl_xor_sync(0xffffffffu, v, o);
        if (lane == 0) zs[t] = fmaxf(v + cb2, 0.0f);
    }
    __syncthreads();

    if (threadIdx.x == 0) {
        const float wih  = w_ih[0];
        const float whh  = w_hh[0];
        const float bias = b_ih[0] + b_hh[0];
        float h = h0[b];
#pragma unroll 3
        for (int t = 0; t < TT; t++) {
            float a = fmaf(wih, zs[t], fmaf(whh, h, bias));
            float e = __expf(2.0f * a);
            h = 1.0f - __fdividef(2.0f, e + 1.0f);   // tanh(a)
        }
        out[bc] = __fdividef(1.0f, 1.0f + __expf(-h));
    }
}

// ---------------- launcher ----------------
extern "C" void kernel_launch(void* const* d_in, const int* in_sizes, int n_in,
                              void* d_out, int out_size) {
    const float* x       = (const float*)d_in[0];
    const float* conv_w  = (const float*)d_in[1];
    const float* conv_b  = (const float*)d_in[2];
    const float* conv2_w = (const float*)d_in[3];
    const float* conv2_b = (const float*)d_in[4];
    const float* w_ih    = (const float*)d_in[5];
    const float* w_hh    = (const float*)d_in[6];
    const float* b_ih    = (const float*)d_in[7];
    const float* b_hh    = (const float*)d_in[8];
    const float* h0      = (const float*)d_in[9];
    float* out = (float*)d_out;

    static int smem_set = 0;
    if (!smem_set) {
        cudaFuncSetAttribute(seg_gemm_mma, cudaFuncAttributeMaxDynamicSharedMemorySize, SMEM_BYTES);
        smem_set = 1;
    }

    pack_w_kernel<<<(NST * NN * BK + 255) / 256, 256>>>(conv_w);

    seg_gemm_mma<<<MM / MTILE, 256, SMEM_BYTES>>>(x);   // 1600 CTAs

    epi_rnn_kernel<<<BB * CC, 128>>>(conv_b, conv2_w, conv2_b,
                                     w_ih, w_hh, b_ih, b_hh, h0, out);
}

// round 14
// speedup vs baseline: 1.3489x; 1.0448x over previous
#include <cuda_runtime.h>
#include <cuda_fp16.h>
#include <cstdint>
#include <math.h>

// ---------------- problem constants ----------------
#define BB   16
#define CC   64
#define WW   125000
#define TT   99
#define SS   100
#define KK   1250        // GEMM K
#define NN   192         // 32 oc * 3 kh * 2 halves
#define BK   64          // K per stage
#define NST  20          // stages (last stage consumes only 48 k)
#define MTILE 64
#define MM   (BB * CC * SS)   // 102400 rows, distinct channels only

// ---------------- scratch ----------------
__device__ __half g_Dh[(size_t)MM * NN];             // 39.3 MB GEMM output (fp16)
__device__ __align__(16) __half g_B[NST * NN * BK];  // packed weights fp16

// ---------------- helpers ----------------
__device__ __forceinline__ uint32_t smem_u32(const void* p) {
    uint32_t a;
    asm("{ .reg .u64 t; cvta.to.shared.u64 t, %1; cvt.u32.u64 %0, t; }" : "=r"(a) : "l"(p));
    return a;
}
#define LDSM4(r0,r1,r2,r3, addr) \
    asm volatile("ldmatrix.sync.aligned.m8n8.x4.shared.b16 {%0,%1,%2,%3}, [%4];" \
        : "=r"(r0),"=r"(r1),"=r"(r2),"=r"(r3) : "r"(addr))
#define CPASYNC16(dst, src) \
    asm volatile("cp.async.cg.shared.global [%0], [%1], 16;" :: "r"(dst), "l"(src))
#define CPCOMMIT() asm volatile("cp.async.commit_group;" ::: "memory")
#define CPWAIT0()  asm volatile("cp.async.wait_group 0;" ::: "memory")

__device__ __forceinline__ void mma16816(float* c, const uint32_t* a, const uint32_t* b) {
    asm volatile("mma.sync.aligned.m16n8k16.row.col.f32.f16.f16.f32 "
        "{%0,%1,%2,%3}, {%4,%5,%6,%7}, {%8,%9}, {%0,%1,%2,%3};"
        : "+f"(c[0]), "+f"(c[1]), "+f"(c[2]), "+f"(c[3])
        : "r"(a[0]), "r"(a[1]), "r"(a[2]), "r"(a[3]), "r"(b[0]), "r"(b[1]));
}

// ---------------- SMEM layout ----------------
#define ASTRIDE 144
#define OFF_B   (MTILE * ASTRIDE)        // 9216
#define BUFSZ   (OFF_B + 192 * ASTRIDE)  // 36864
#define SMEM_BYTES (2 * BUFSZ)           // 73728 -> 2 CTAs/SM

// ---------------- kernel 0: pack weights -> fp16 (half2 path) ----------------
__global__ void pack_w_kernel(const float* __restrict__ conv_w) {
    int i = blockIdx.x * blockDim.x + threadIdx.x;     // pair index
    if (i >= NST * NN * BK / 2) return;
    int c = i / (NN * BK / 2);
    int r = i - c * (NN * BK / 2);
    int n = r >> 5;              // 0..191
    int kp = r & 31;             // pair within stage
    int kk = c * BK + kp * 2;
    int grp = n >> 5;
    int oc  = n & 31;
    int kh  = grp >> 1;
    int h   = grp & 1;
    float2 w = make_float2(0.0f, 0.0f);
    if (kk < KK)                 // KK even -> pair fully in or out
        w = *reinterpret_cast<const float2*>(conv_w + oc * 7500 + kh * 2500 + h * 1250 + kk);
    reinterpret_cast<__half2*>(g_B)[i] = __floats2half2_rn(w.x, w.y);
}

// ---------------- kernel 1: fp16 HMMA segment GEMM, 256 threads, 2 CTAs/SM ----------------
__global__ __launch_bounds__(256, 2) void seg_gemm_mma(const float* __restrict__ x) {
    extern __shared__ char smem[];
    const uint32_t sb = smem_u32(smem);
    const int tid  = threadIdx.x;
    const int wid  = tid >> 5;
    const int lane = tid & 31;

    // per-warp A rows: 8 consecutive rows; lane offset = lane*2 floats
    const int rowbase = wid * 8;
    const float* rowp[8];
#pragma unroll
    for (int i = 0; i < 8; i++) {
        int m = blockIdx.x * MTILE + rowbase + i;
        int bc = m / SS;
        int s  = m - bc * SS;
        rowp[i] = x + (size_t)bc * WW + (size_t)s * KK + lane * 2;
    }

    const int warpM = (wid & 1) * 32;
    const int warpN = (wid >> 1) * 48;
    const uint32_t invA = (uint32_t)((warpM + (lane & 15)) * ASTRIDE + ((lane >> 4) * 16));
    const uint32_t invB = (uint32_t)((warpN + (lane & 7) + ((lane & 16) >> 1)) * ASTRIDE + ((lane & 8) << 1));

    float acc[2][6][4];
#pragma unroll
    for (int i = 0; i < 2; i++)
#pragma unroll
        for (int j = 0; j < 6; j++)
#pragma unroll
            for (int q = 0; q < 4; q++) acc[i][j][q] = 0.0f;

    float2 f2[8];

    auto loadA = [&](int c) {
        if (c < NST - 1) {
#pragma unroll
            for (int i = 0; i < 8; i++)
                f2[i] = *reinterpret_cast<const float2*>(rowp[i] + c * BK);
        } else {
            const int k0 = c * BK + lane * 2;
            if (k0 < KK) {
#pragma unroll
                for (int i = 0; i < 8; i++)
                    f2[i] = *reinterpret_cast<const float2*>(rowp[i] + c * BK);
            } else {
#pragma unroll
                for (int i = 0; i < 8; i++) f2[i] = make_float2(0.0f, 0.0f);
            }
        }
    };
    auto stsA = [&](int buf) {
        const uint32_t base = sb + buf * BUFSZ + rowbase * ASTRIDE + lane * 4;
#pragma unroll
        for (int i = 0; i < 8; i++) {
            __half2 hh = __floats2half2_rn(f2[i].x, f2[i].y);
            asm volatile("st.shared.b32 [%0], %1;"
                :: "r"(base + i * ASTRIDE), "r"(*reinterpret_cast<uint32_t*>(&hh)) : "memory");
        }
    };
    auto loadB = [&](int c, int buf) {
#pragma unroll
        for (int i = 0; i < 6; i++) {
            int u = tid + 256 * i;
            int rowb = u >> 3, j = u & 7;
            uint32_t dst = sb + buf * BUFSZ + OFF_B + rowb * ASTRIDE + j * 16;
            const char* src = reinterpret_cast<const char*>(g_B) + ((size_t)c * NN + rowb) * 128 + j * 16;
            CPASYNC16(dst, src);
        }
    };

    // full stage: 4 k-groups; tail stage: 3 k-groups (k 1216..1263, weights 0 past 1250)
    auto compute4 = [&](int buf) {
        const uint32_t ab = sb + buf * BUFSZ;
#pragma unroll
        for (int g = 0; g < 4; g++) {
            uint32_t ah[8];
            LDSM4(ah[0], ah[1], ah[2], ah[3], ab + invA + g * 32);
            LDSM4(ah[4], ah[5], ah[6], ah[7], ab + invA + 16 * ASTRIDE + g * 32);
#pragma unroll
            for (int ng = 0; ng < 3; ng++) {
                uint32_t bf[4];
                LDSM4(bf[0], bf[1], bf[2], bf[3], ab + OFF_B + invB + ng * (16 * ASTRIDE) + g * 32);
#pragma unroll
                for (int mt = 0; mt < 2; mt++) {
                    mma16816(acc[mt][ng * 2 + 0], ah + mt * 4, bf + 0);
                    mma16816(acc[mt][ng * 2 + 1], ah + mt * 4, bf + 2);
                }
            }
        }
    };
    auto compute3 = [&](int buf) {
        const uint32_t ab = sb + buf * BUFSZ;
#pragma unroll
        for (int g = 0; g < 3; g++) {
            uint32_t ah[8];
            LDSM4(ah[0], ah[1], ah[2], ah[3], ab + invA + g * 32);
            LDSM4(ah[4], ah[5], ah[6], ah[7], ab + invA + 16 * ASTRIDE + g * 32);
#pragma unroll
            for (int ng = 0; ng < 3; ng++) {
                uint32_t bf[4];
                LDSM4(bf[0], bf[1], bf[2], bf[3], ab + OFF_B + invB + ng * (16 * ASTRIDE) + g * 32);
#pragma unroll
                for (int mt = 0; mt < 2; mt++) {
                    mma16816(acc[mt][ng * 2 + 0], ah + mt * 4, bf + 0);
                    mma16816(acc[mt][ng * 2 + 1], ah + mt * 4, bf + 2);
                }
            }
        }
    };

    // prologue
    loadA(0);
    loadB(0, 0);
    CPCOMMIT();
    stsA(0);
    CPWAIT0();
    __syncthreads();

    // main loop
    for (int c = 0; c < NST; c++) {
        const int buf = c & 1;
        if (c < NST - 1) { loadA(c + 1); loadB(c + 1, buf ^ 1); CPCOMMIT(); }
        if (c < NST - 1) compute4(buf); else compute3(buf);
        if (c < NST - 1) { stsA(buf ^ 1); CPWAIT0(); }
        __syncthreads();
    }

    // write D (fp16)
    const int l4 = lane >> 2;
    const int l2 = (lane & 3) * 2;
#pragma unroll
    for (int mt = 0; mt < 2; mt++) {
        const int mrow = blockIdx.x * MTILE + warpM + mt * 16 + l4;
        __half* dbase = g_Dh + (size_t)mrow * NN + warpN + l2;
#pragma unroll
        for (int nt = 0; nt < 6; nt++) {
            *reinterpret_cast<__half2*>(dbase + nt * 8)          = __floats2half2_rn(acc[mt][nt][0], acc[mt][nt][1]);
            *reinterpret_cast<__half2*>(dbase + nt * 8 + 8 * NN) = __floats2half2_rn(acc[mt][nt][2], acc[mt][nt][3]);
        }
    }
}

// ---------------- kernel 2: fused combine + 1x1 conv + RNN scan + sigmoid ----------------
// half2 oc-pairs; lane bit4 selects t vs t+1 (2 time steps per warp-iteration).
__global__ __launch_bounds__(128) void epi_rnn_kernel(
        const float* __restrict__ conv_b,  const float* __restrict__ conv2_w,
        const float* __restrict__ conv2_b,
        const float* __restrict__ w_ih, const float* __restrict__ w_hh,
        const float* __restrict__ b_ih, const float* __restrict__ b_hh,
        const float* __restrict__ h0,   float* __restrict__ out) {
    __shared__ float zs[TT];
    const int bc = blockIdx.x;
    const int b = bc >> 6;
    const int c = bc & 63;
    const int wid  = threadIdx.x >> 5;
    const int lane = threadIdx.x & 31;
    const int sub  = lane >> 4;          // 0: t, 1: t+1
    const int l    = lane & 15;          // oc pair index

    const float2 cbp = reinterpret_cast<const float2*>(conv_b)[l];
    const float2 cwp = reinterpret_cast<const float2*>(conv2_w)[l];
    const float  cb2 = conv2_b[0];

    int chrow[3];
#pragma unroll
    for (int kh = 0; kh < 3; kh++) {
        int ch = c + kh - 1; ch = ch < 0 ? 0 : (ch > 63 ? 63 : ch);
        chrow[kh] = b * CC + ch;
    }

    // warp handles t pair (2*wid + 8*i, +1)
    for (int t0 = wid * 2; t0 < TT; t0 += 8) {
        const int t = t0 + sub;
        float sx = 0.0f, sy = 0.0f;
        if (t < TT) {
#pragma unroll
            for (int kh = 0; kh < 3; kh++) {
#pragma unroll
                for (int h = 0; h < 2; h++) {
                    size_t row = (size_t)chrow[kh] * SS + (t + h);
                    __half2 v = *reinterpret_cast<const __half2*>(
                        g_Dh + row * NN + (kh * 2 + h) * 32 + 2 * l);
                    float2 f = __half22float2(v);
                    sx += f.x; sy += f.y;
                }
            }
        }
        float yx = fmaxf(sx + cbp.x, 0.0f);
        float yy = fmaxf(sy + cbp.y, 0.0f);
        float v = yx * cwp.x + yy * cwp.y;
#pragma unroll
        for (int o = 8; o > 0; o >>= 1)
            v += __shfl_xor_sync(0xffffffffu, v, o);
        if (l == 0 && t < TT) zs[t] = fmaxf(v + cb2, 0.0f);
    }
    __syncthreads();

    if (threadIdx.x == 0) {
        const float wih  = w_ih[0];
        const float whh  = w_hh[0];
        const float bias = b_ih[0] + b_hh[0];
        float h = h0[b];
#pragma unroll 3
        for (int t = 0; t < TT; t++) {
            float a = fmaf(wih, zs[t], fmaf(whh, h, bias));
            float e = __expf(2.0f * a);
            h = 1.0f - __fdividef(2.0f, e + 1.0f);   // tanh(a)
        }
        out[bc] = __fdividef(1.0f, 1.0f + __expf(-h));
    }
}

// ---------------- launcher ----------------
extern "C" void kernel_launch(void* const* d_in, const int* in_sizes, int n_in,
                              void* d_out, int out_size) {
    const float* x       = (const float*)d_in[0];
    const float* conv_w  = (const float*)d_in[1];
    const float* conv_b  = (const float*)d_in[2];
    const float* conv2_w = (const float*)d_in[3];
    const float* conv2_b = (const float*)d_in[4];
    const float* w_ih    = (const float*)d_in[5];
    const float* w_hh    = (const float*)d_in[6];
    const float* b_ih    = (const float*)d_in[7];
    const float* b_hh    = (const float*)d_in[8];
    const float* h0      = (const float*)d_in[9];
    float* out = (float*)d_out;

    static int smem_set = 0;
    if (!smem_set) {
        cudaFuncSetAttribute(seg_gemm_mma, cudaFuncAttributeMaxDynamicSharedMemorySize, SMEM_BYTES);
        smem_set = 1;
    }

    pack_w_kernel<<<(NST * NN * BK / 2 + 255) / 256, 256>>>(conv_w);

    seg_gemm_mma<<<MM / MTILE, 256, SMEM_BYTES>>>(x);   // 1600 CTAs

    epi_rnn_kernel<<<BB * CC, 128>>>(conv_b, conv2_w, conv2_b,
                                     w_ih, w_hh, b_ih, b_hh, h0, out);
}